// round 9
// baseline (speedup 1.0000x reference)
#include <cuda_runtime.h>
#include <cstdint>

#define A_STRIDE 132                     // words
#define B_STRIDE 264                     // words; frag banks lc*8+lr, conflict-free
#define KCHUNK 16
#define NCHUNK 8
#define A_WORDS (128 * A_STRIDE)         // 16896
#define B_WORDS (KCHUNK * B_STRIDE)      // 4224
#define SMEM_BYTES ((2 * A_WORDS + 4 * B_WORDS) * 4)   // 202752

__device__ unsigned g_bar[32];           // per-batch barrier tickets (monotonic, replay-safe)

static __device__ __forceinline__ uint32_t tf32u(float x) {
    uint32_t r;
    asm("cvt.rna.tf32.f32 %0, %1;" : "=r"(r) : "f"(x));
    return r;
}
static __device__ __forceinline__ void cp16(uint32_t dst, const void* src) {
    asm volatile("cp.async.cg.shared.global [%0], [%1], 16;" :: "r"(dst), "l"(src));
}
#define CP_COMMIT() asm volatile("cp.async.commit_group;" ::: "memory")
#define CP_WAIT(n)  asm volatile("cp.async.wait_group %0;" :: "n"(n) : "memory")

static __device__ __forceinline__ void ldsm_x4(uint32_t r[4], uint32_t addr) {
    asm volatile("ldmatrix.sync.aligned.m8n8.x4.shared.b16 {%0,%1,%2,%3}, [%4];"
                 : "=r"(r[0]), "=r"(r[1]), "=r"(r[2]), "=r"(r[3]) : "r"(addr));
}
static __device__ __forceinline__ void mma_tf32(float c[4], const uint32_t a[4],
                                                uint32_t b0, uint32_t b1) {
    asm volatile(
        "mma.sync.aligned.m16n8k8.row.col.f32.tf32.tf32.f32 "
        "{%0,%1,%2,%3}, {%4,%5,%6,%7}, {%8,%9}, {%0,%1,%2,%3};"
        : "+f"(c[0]), "+f"(c[1]), "+f"(c[2]), "+f"(c[3])
        : "r"(a[0]), "r"(a[1]), "r"(a[2]), "r"(a[3]), "r"(b0), "r"(b1));
}

// ---------------------------------------------------------------------------
// Fused persistent kernel, grid = 128 CTAs x 512 thr, 1 CTA/SM (all resident).
// CTA rc processes 2B tiles in order: s even -> term1(b=s/2) tile (b, rc):
//   out[b,rc,:,:] = softmax(attn_x[b,rc]+g) @ V[b,rc]          (overwrite)
// s odd -> term2(b) tile (b, rc):
//   out[b,:,rc,:] += softmax(attn_y[b,rc]+g) @ V[b,:,rc,:]     (RMW)
// Per-batch global barrier: arrive after term1(b) epilogue; wait just before
// term2(b) epilogue (overlapped by term2's softmax+MMA). out[b] + V[b] stay
// hot in L2 between the phases.
// ---------------------------------------------------------------------------
__global__ void __launch_bounds__(512, 1) gt_fused(
    const float* __restrict__ attn_x, const float* __restrict__ attn_y,
    const float* __restrict__ V,
    const float* __restrict__ sp, const float* __restrict__ bp,
    float* __restrict__ out, int B)
{
    extern __shared__ uint32_t smem[];
    uint32_t* Ab[2] = { smem, smem + A_WORDS };
    uint32_t* Bb = smem + 2 * A_WORDS;               // 4 ring buffers
    uint32_t Au[2];
    Au[0] = (uint32_t)__cvta_generic_to_shared(Ab[0]);
    Au[1] = (uint32_t)__cvta_generic_to_shared(Ab[1]);
    const uint32_t Bu = (uint32_t)__cvta_generic_to_shared(Bb);

    const int tid = threadIdx.x, lane = tid & 31, wid = tid >> 5;
    const int rc = blockIdx.x;
    const unsigned G = gridDim.x;
    const float sh = sp[0], bi = bp[0];
    const int S = 2 * B;

    auto vstride_of = [&](int s) -> size_t { return (s & 1) ? (size_t)32768 : (size_t)256; };
    auto off_of = [&](int s) -> size_t {
        int b = s >> 1;
        return (s & 1) ? ((size_t)b * 4194304 + (size_t)rc * 256)
                       : (((size_t)b * 128 + rc) * (size_t)32768);
    };
    auto issue_A = [&](int s, int p) {
        int b = s >> 1;
        const float* src = ((s & 1) ? attn_y : attn_x)
                           + ((size_t)b * 128 + rc) * (size_t)16384;
        #pragma unroll
        for (int i = 0; i < 8; ++i) {
            int c = i * 512 + tid;                   // 4096 16B chunks
            int row = c >> 5, q = c & 31;
            cp16(Au[p] + (uint32_t)row * (A_STRIDE * 4) + (uint32_t)q * 16,
                 src + row * 128 + q * 4);
        }
        CP_COMMIT();
    };
    auto issue_B = [&](int s, int chunk) {
        const size_t vs = vstride_of(s);
        const float* src = V + off_of(s) + (size_t)(chunk * KCHUNK) * vs;
        const uint32_t dst = Bu + (uint32_t)(chunk & 3) * (B_WORDS * 4);
        #pragma unroll
        for (int i = 0; i < 2; ++i) {
            int c = i * 512 + tid;                   // 1024 chunks: 16 rows x 64 q
            int row = c >> 6, q = c & 63;
            cp16(dst + (uint32_t)row * (B_STRIDE * 4) + (uint32_t)q * 16,
                 src + (size_t)row * vs + q * 4);
        }
        CP_COMMIT();
    };

    int p = 0;
    issue_A(0, 0);
    issue_B(0, 0);
    issue_B(0, 1);
    issue_B(0, 2);

    const int mh = (wid & 1) * 64;
    const int nq = (wid >> 1) * 32;
    const int lr = lane >> 2, lc = lane & 3;
    const int lm_mat = lane >> 3, lm_row = lane & 7;
    const int lm_roff = (lm_mat & 1) * 8 + lm_row;
    const int lm_koff = (lm_mat >> 1) * 4;

    unsigned tick = 0;                               // tid0's barrier ticket

    #pragma unroll 1
    for (int s = 0; s < S; ++s) {
        const bool last = (s == S - 1);
        const int term = s & 1, b = s >> 1;
        const size_t vstride = vstride_of(s);
        const size_t off = off_of(s);

        // ---- head: A(s) ready ----
        CP_WAIT(3);
        __syncthreads();

        // ---- softmax in place (no max pass; exponents bounded) ----
        float* Af = (float*)Ab[p];
        #pragma unroll 1
        for (int rr = 0; rr < 8; ++rr) {
            int row = wid * 8 + rr;
            float4 v = *(const float4*)(Af + row * A_STRIDE + lane * 4);
            float fr = (float)row;
            float e[4]; float sum = 0.f;
            #pragma unroll
            for (int j = 0; j < 4; ++j) {
                float d = (float)(lane * 4 + j) - fr;
                float vv = (j == 0 ? v.x : j == 1 ? v.y : j == 2 ? v.z : v.w)
                           - fmaf(sh, d * d, bi);
                e[j] = __expf(vv);
                sum += e[j];
            }
            #pragma unroll
            for (int o = 16; o > 0; o >>= 1) sum += __shfl_xor_sync(~0u, sum, o);
            float inv = 1.0f / sum;
            uint4 w = make_uint4(tf32u(e[0] * inv), tf32u(e[1] * inv),
                                 tf32u(e[2] * inv), tf32u(e[3] * inv));
            *(uint4*)(Ab[p] + row * A_STRIDE + lane * 4) = w;
        }
        __syncthreads();

        if (!last) issue_A(s + 1, p ^ 1);

        float acc[4][4][4];
        #pragma unroll
        for (int u = 0; u < 4; ++u)
            #pragma unroll
            for (int j = 0; j < 4; ++j)
                #pragma unroll
                for (int q = 0; q < 4; ++q) acc[u][j][q] = 0.f;

        // ---- 8 k-chunks of 16, 4-buffer ring (same FIFO schedule as R8) ----
        #pragma unroll 1
        for (int c = 0; c < NCHUNK; ++c) {
            if (!last) {
                if (c <= 2) CP_WAIT(3); else CP_WAIT(2);
            } else {
                if (c <= 5) CP_WAIT(2);
                else if (c == 6) CP_WAIT(1);
                else CP_WAIT(0);
            }
            __syncthreads();

            if (c <= 4) issue_B(s, c + 3);
            else if (!last) issue_B(s + 1, c - 5);

            const uint32_t* Bsc = Bb + (c & 3) * B_WORDS;
            #pragma unroll
            for (int ks = 0; ks < 2; ++ks) {
                uint32_t a[4][4];
                #pragma unroll
                for (int u = 0; u < 4; ++u) {
                    uint32_t addr = Au[p] + (uint32_t)((mh + u * 16 + lm_roff) * A_STRIDE
                                                       + c * KCHUNK + ks * 8 + lm_koff) * 4;
                    ldsm_x4(a[u], addr);
                }
                #pragma unroll
                for (int j = 0; j < 4; ++j) {
                    const float* bp8 = (const float*)Bsc + (ks * 8 + lc) * B_STRIDE
                                       + nq + j * 8 + lr;
                    uint32_t b0 = tf32u(bp8[0]);
                    uint32_t b1 = tf32u(bp8[4 * B_STRIDE]);
                    #pragma unroll
                    for (int u = 0; u < 4; ++u)
                        mma_tf32(acc[u][j], a[u], b0, b1);
                }
            }
        }

        // ---- barrier wait (term2 only): term1(b) writes must be visible ----
        if (term) {
            if (tid == 0) {
                unsigned target = (tick / G + 1u) * G;
                while (*(volatile unsigned*)&g_bar[b] < target) __nanosleep(100);
                __threadfence();
            }
            __syncthreads();
        }

        // ---- epilogue ----
        float* obase = out + off;
        #pragma unroll
        for (int u = 0; u < 4; ++u) {
            #pragma unroll
            for (int j = 0; j < 4; ++j) {
                int r0 = mh + u * 16 + lr;
                int col = nq + j * 8 + lc * 2;
                float* p0 = obase + (size_t)r0 * vstride + col;
                float* p1 = p0 + 8 * vstride;
                float2 v0 = make_float2(acc[u][j][0], acc[u][j][1]);
                float2 v1 = make_float2(acc[u][j][2], acc[u][j][3]);
                if (term) {
                    float2 c0 = __ldcg((const float2*)p0);
                    float2 c1 = __ldcg((const float2*)p1);
                    v0.x += c0.x; v0.y += c0.y;
                    v1.x += c1.x; v1.y += c1.y;
                }
                *(float2*)p0 = v0;
                *(float2*)p1 = v1;
            }
        }

        // ---- barrier arrive (term1 only) ----
        if (!term) {
            __threadfence();
            __syncthreads();
            if (tid == 0) tick = atomicAdd(&g_bar[b], 1u);
        }

        p ^= 1;
    }
}

extern "C" void kernel_launch(void* const* d_in, const int* in_sizes, int n_in,
                              void* d_out, int out_size)
{
    const float* attn_x = (const float*)d_in[1];
    const float* attn_y = (const float*)d_in[2];
    const float* V      = (const float*)d_in[3];
    const float* sh     = (const float*)d_in[4];
    const float* bi     = (const float*)d_in[5];
    float* out          = (float*)d_out;

    const int B = in_sizes[3] / (128 * 128 * 256);

    cudaFuncSetAttribute(gt_fused, cudaFuncAttributeMaxDynamicSharedMemorySize, SMEM_BYTES);

    gt_fused<<<128, 512, SMEM_BYTES>>>(attn_x, attn_y, V, sh, bi, out, B);
}

// round 11
// speedup vs baseline: 1.0136x; 1.0136x over previous
#include <cuda_runtime.h>
#include <cstdint>

#define A_STRIDE 132                     // words
#define B_STRIDE 264                     // words
#define KCHUNK 16
#define NCHUNK 8
#define A_WORDS (128 * A_STRIDE)         // 16896
#define B_WORDS (KCHUNK * B_STRIDE)      // 4224
#define SMEM_BYTES ((2 * A_WORDS + 4 * B_WORDS) * 4)   // 202752

__device__ unsigned g_bar[32];           // per-batch tickets (monotonic, replay-safe)

static __device__ __forceinline__ uint32_t tf32u(float x) {
    uint32_t r;
    asm("cvt.rna.tf32.f32 %0, %1;" : "=r"(r) : "f"(x));
    return r;
}
static __device__ __forceinline__ void cp16(uint32_t dst, const void* src) {
    asm volatile("cp.async.cg.shared.global [%0], [%1], 16;" :: "r"(dst), "l"(src));
}
#define CP_COMMIT() asm volatile("cp.async.commit_group;" ::: "memory")
#define CP_WAIT(n)  asm volatile("cp.async.wait_group %0;" :: "n"(n) : "memory")

static __device__ __forceinline__ void pair_bar(int id) {
    asm volatile("bar.sync %0, 64;" :: "r"(id) : "memory");
}
static __device__ __forceinline__ void ldsm_x4(uint32_t r[4], uint32_t addr) {
    asm volatile("ldmatrix.sync.aligned.m8n8.x4.shared.b16 {%0,%1,%2,%3}, [%4];"
                 : "=r"(r[0]), "=r"(r[1]), "=r"(r[2]), "=r"(r[3]) : "r"(addr));
}
static __device__ __forceinline__ void mma_tf32(float c[4], const uint32_t a[4],
                                                uint32_t b0, uint32_t b1) {
    asm volatile(
        "mma.sync.aligned.m16n8k8.row.col.f32.tf32.tf32.f32 "
        "{%0,%1,%2,%3}, {%4,%5,%6,%7}, {%8,%9}, {%0,%1,%2,%3};"
        : "+f"(c[0]), "+f"(c[1]), "+f"(c[2]), "+f"(c[3])
        : "r"(a[0]), "r"(a[1]), "r"(a[2]), "r"(a[3]), "r"(b0), "r"(b1));
}

// ---------------------------------------------------------------------------
// Fused persistent kernel, 128 CTAs x 512 thr.
// Phase order: t1(0), t1(1), t2(0), t1(2), t2(1), ..., t1(B-1), t2(B-2), t2(B-1)
//   t1(b): out[b,rc,:,:]  = softmax(attn_x[b,rc]+g) @ V[b,rc]       (overwrite)
//   t2(b): out[b,:,rc,:] += softmax(attn_y[b,rc]+g) @ V[b,:,rc,:]   (RMW, L2-hot)
// B: 4-buffer ring; warp pair (2k,2k+1) shares slab [16k x 32n]; both issue
// identical copies (own wait_group visibility); pairwise named bar.sync at the
// top of each chunk guards slab generation reuse. No block syncs in chunk loop.
// ---------------------------------------------------------------------------
__global__ void __launch_bounds__(512, 1) gt_fused(
    const float* __restrict__ attn_x, const float* __restrict__ attn_y,
    const float* __restrict__ V,
    const float* __restrict__ sp, const float* __restrict__ bp,
    float* __restrict__ out, int B)
{
    extern __shared__ uint32_t smem[];
    uint32_t* Ab[2] = { smem, smem + A_WORDS };
    uint32_t* Bb = smem + 2 * A_WORDS;
    uint32_t Au[2];
    Au[0] = (uint32_t)__cvta_generic_to_shared(Ab[0]);
    Au[1] = (uint32_t)__cvta_generic_to_shared(Ab[1]);
    const uint32_t Bu = (uint32_t)__cvta_generic_to_shared(Bb);

    const int tid = threadIdx.x, lane = tid & 31, wid = tid >> 5;
    const int rc = blockIdx.x;
    const unsigned G = gridDim.x;
    const float sh = sp[0], bi = bp[0];
    const int S = 2 * B;

    const int mh = (wid & 1) * 64;
    const int nq = (wid >> 1) * 32;
    const int pb = (wid >> 1) + 1;        // named barrier id 1..8 per pair
    const int lr = lane >> 2, lc = lane & 3;
    const int lm_mat = lane >> 3, lm_row = lane & 7;
    const int lm_roff = (lm_mat & 1) * 8 + lm_row;
    const int lm_koff = (lm_mat >> 1) * 4;

    auto term_of = [&](int i) -> int {
        return (i == 0 || ((i & 1) && i < S - 1)) ? 0 : 1;
    };
    auto b_of = [&](int i) -> int {
        if (i == 0) return 0;
        if ((i & 1) && i < S - 1) return (i + 1) >> 1;   // t1
        if (i == S - 1) return B - 1;                    // final t2
        return (i - 2) >> 1;                             // t2
    };
    auto vs_of  = [&](int i) -> size_t { return term_of(i) ? (size_t)32768 : (size_t)256; };
    auto off_of = [&](int i) -> size_t {
        int b = b_of(i);
        return term_of(i) ? ((size_t)b * 4194304 + (size_t)rc * 256)
                          : (((size_t)b * 128 + rc) * (size_t)32768);
    };
    auto issue_A = [&](int i, int p) {
        const float* base = term_of(i) ? attn_y : attn_x;
        const float* src = base + ((size_t)b_of(i) * 128 + rc) * (size_t)16384;
        #pragma unroll
        for (int q = 0; q < 8; ++q) {
            int c = q * 512 + tid;
            int row = c >> 5, w = c & 31;
            cp16(Au[p] + (uint32_t)row * (A_STRIDE * 4) + (uint32_t)w * 16,
                 src + row * 128 + w * 4);
        }
        CP_COMMIT();
    };
    // warp copies the pair's 16k x 32n slab (partner writes identical bytes)
    auto issue_B = [&](int i, int chunk) {
        const size_t vs = vs_of(i);
        const float* src = V + off_of(i) + (size_t)(chunk * KCHUNK) * vs + nq;
        const uint32_t dst = Bu + (uint32_t)(chunk & 3) * (B_WORDS * 4)
                           + (uint32_t)nq * 4;
        #pragma unroll
        for (int q = 0; q < 4; ++q) {
            int c = q * 32 + lane;               // 128 chunks: 16 rows x 8 x 16B
            int row = c >> 3, g = c & 7;
            cp16(dst + (uint32_t)row * (B_STRIDE * 4) + (uint32_t)g * 16,
                 src + (size_t)row * vs + g * 4);
        }
        CP_COMMIT();
    };

    int p = 0;
    issue_A(0, 0);
    issue_B(0, 0);
    issue_B(0, 1);
    issue_B(0, 2);

    unsigned tick = 0;

    #pragma unroll 1
    for (int i = 0; i < S; ++i) {
        const bool lastp = (i == S - 1);
        const int term = term_of(i), b = b_of(i);
        const size_t vstride = vs_of(i);
        const size_t off = off_of(i);

        // ---- head: A(i) ready for every thread's own groups ----
        CP_WAIT(3);
        __syncthreads();

        // ---- softmax in place (no max pass; exponents bounded) ----
        float* Af = (float*)Ab[p];
        #pragma unroll 1
        for (int rr = 0; rr < 8; ++rr) {
            int row = wid * 8 + rr;
            float4 v = *(const float4*)(Af + row * A_STRIDE + lane * 4);
            float fr = (float)row;
            float e[4]; float sum = 0.f;
            #pragma unroll
            for (int j = 0; j < 4; ++j) {
                float d = (float)(lane * 4 + j) - fr;
                float vv = (j == 0 ? v.x : j == 1 ? v.y : j == 2 ? v.z : v.w)
                           - fmaf(sh, d * d, bi);
                e[j] = __expf(vv);
                sum += e[j];
            }
            #pragma unroll
            for (int o = 16; o > 0; o >>= 1) sum += __shfl_xor_sync(~0u, sum, o);
            float inv = 1.0f / sum;
            uint4 w = make_uint4(tf32u(e[0] * inv), tf32u(e[1] * inv),
                                 tf32u(e[2] * inv), tf32u(e[3] * inv));
            *(uint4*)(Ab[p] + row * A_STRIDE + lane * 4) = w;
        }
        __syncthreads();

        if (!lastp) issue_A(i + 1, p ^ 1);

        float acc[4][4][4];
        #pragma unroll
        for (int u = 0; u < 4; ++u)
            #pragma unroll
            for (int j = 0; j < 4; ++j)
                #pragma unroll
                for (int q = 0; q < 4; ++q) acc[u][j][q] = 0.f;

        // ---- 8 k-chunks, pair-paced (named bar per chunk, no block syncs) ----
        #pragma unroll 1
        for (int c = 0; c < NCHUNK; ++c) {
            // partner past chunk c-1 reads -> safe to overwrite slab gen c-1
            pair_bar(pb);

            if (!lastp) {
                if (c <= 2) CP_WAIT(3); else CP_WAIT(2);
            } else {
                if (c <= 5) CP_WAIT(2);
                else if (c == 6) CP_WAIT(1);
                else CP_WAIT(0);
            }

            if (c <= 4) issue_B(i, c + 3);
            else if (!lastp) issue_B(i + 1, c - 5);

            const uint32_t* Bsc = Bb + (c & 3) * B_WORDS;
            #pragma unroll
            for (int ks = 0; ks < 2; ++ks) {
                uint32_t a[4][4];
                #pragma unroll
                for (int u = 0; u < 4; ++u) {
                    uint32_t addr = Au[p] + (uint32_t)((mh + u * 16 + lm_roff) * A_STRIDE
                                                       + c * KCHUNK + ks * 8 + lm_koff) * 4;
                    ldsm_x4(a[u], addr);
                }
                #pragma unroll
                for (int j = 0; j < 4; ++j) {
                    const float* bp8 = (const float*)Bsc + (ks * 8 + lc) * B_STRIDE
                                       + nq + j * 8 + lr;
                    uint32_t b0 = tf32u(bp8[0]);
                    uint32_t b1 = tf32u(bp8[4 * B_STRIDE]);
                    #pragma unroll
                    for (int u = 0; u < 4; ++u)
                        mma_tf32(acc[u][j], a[u], b0, b1);
                }
            }
        }

        // ---- barrier wait (term2): t1(b) writes visible; 1 phase of slack ----
        if (term) {
            if (tid == 0) {
                unsigned target = (tick / G + 1u) * G;
                while (*(volatile unsigned*)&g_bar[b] < target) __nanosleep(64);
                __threadfence();
            }
            __syncthreads();
        }

        // ---- epilogue ----
        float* obase = out + off;
        #pragma unroll
        for (int u = 0; u < 4; ++u) {
            #pragma unroll
            for (int j = 0; j < 4; ++j) {
                int r0 = mh + u * 16 + lr;
                int col = nq + j * 8 + lc * 2;
                float* p0 = obase + (size_t)r0 * vstride + col;
                float* p1 = p0 + 8 * vstride;
                float2 v0 = make_float2(acc[u][j][0], acc[u][j][1]);
                float2 v1 = make_float2(acc[u][j][2], acc[u][j][3]);
                if (term) {
                    float2 c0 = __ldcg((const float2*)p0);
                    float2 c1 = __ldcg((const float2*)p1);
                    v0.x += c0.x; v0.y += c0.y;
                    v1.x += c1.x; v1.y += c1.y;
                }
                *(float2*)p0 = v0;
                *(float2*)p1 = v1;
            }
        }

        // ---- barrier arrive (term1) ----
        if (!term) {
            __threadfence();
            __syncthreads();
            if (tid == 0) tick = atomicAdd(&g_bar[b], 1u);
        }

        p ^= 1;
    }
}

extern "C" void kernel_launch(void* const* d_in, const int* in_sizes, int n_in,
                              void* d_out, int out_size)
{
    const float* attn_x = (const float*)d_in[1];
    const float* attn_y = (const float*)d_in[2];
    const float* V      = (const float*)d_in[3];
    const float* sh     = (const float*)d_in[4];
    const float* bi     = (const float*)d_in[5];
    float* out          = (float*)d_out;

    const int B = in_sizes[3] / (128 * 128 * 256);

    cudaFuncSetAttribute(gt_fused, cudaFuncAttributeMaxDynamicSharedMemorySize, SMEM_BYTES);

    gt_fused<<<128, 512, SMEM_BYTES>>>(attn_x, attn_y, V, sh, bi, out, B);
}

// round 12
// speedup vs baseline: 1.3210x; 1.3032x over previous
#include <cuda_runtime.h>
#include <cstdint>

#define A_STRIDE 132                     // words
#define B_STRIDE 264                     // words
#define KCHUNK 16
#define NCHUNK 8
#define A_WORDS (64 * A_STRIDE)          // 8448 (64-row half tile)
#define B_WORDS (KCHUNK * B_STRIDE)      // 4224
#define SMEM_BYTES ((A_WORDS + 4 * B_WORDS) * 4)   // 33792 + 67584 = 101376

static __device__ __forceinline__ uint32_t tf32u(float x) {
    uint32_t r;
    asm("cvt.rna.tf32.f32 %0, %1;" : "=r"(r) : "f"(x));
    return r;
}
static __device__ __forceinline__ void cp16(uint32_t dst, const void* src) {
    asm volatile("cp.async.cg.shared.global [%0], [%1], 16;" :: "r"(dst), "l"(src));
}
#define CP_COMMIT() asm volatile("cp.async.commit_group;" ::: "memory")
#define CP_WAIT(n)  asm volatile("cp.async.wait_group %0;" :: "n"(n) : "memory")

static __device__ __forceinline__ void ldsm_x4(uint32_t r[4], uint32_t addr) {
    asm volatile("ldmatrix.sync.aligned.m8n8.x4.shared.b16 {%0,%1,%2,%3}, [%4];"
                 : "=r"(r[0]), "=r"(r[1]), "=r"(r[2]), "=r"(r[3]) : "r"(addr));
}
static __device__ __forceinline__ void mma_tf32(float c[4], const uint32_t a[4],
                                                uint32_t b0, uint32_t b1) {
    asm volatile(
        "mma.sync.aligned.m16n8k8.row.col.f32.tf32.tf32.f32 "
        "{%0,%1,%2,%3}, {%4,%5,%6,%7}, {%8,%9}, {%0,%1,%2,%3};"
        : "+f"(c[0]), "+f"(c[1]), "+f"(c[2]), "+f"(c[3])
        : "r"(a[0]), "r"(a[1]), "r"(a[2]), "r"(a[3]), "r"(b0), "r"(b1));
}

// ---------------------------------------------------------------------------
// Persistent, 256 thr/CTA, 2 CTAs/SM. Half-tile t -> (mhh = (t&1)*64,
// rc = (t>>1)&127, b = t>>8): D[64,256] = softmax(attn[b,rc, mhh..]+g) @ V_t.
// 8 warps, warp w: full 64 m-rows x n-cols [w*32, w*32+32) -> B slab private.
// Chunk loop: zero block syncs; per-warp cp.async FIFO paces everything.
// Per tile: 3 block syncs (tile-end issue, head, post-softmax).
// ---------------------------------------------------------------------------
__global__ void __launch_bounds__(256, 2) gt_mma(
    const float* __restrict__ attn, const float* __restrict__ V,
    const float* __restrict__ sp, const float* __restrict__ bp,
    float* __restrict__ out, int term, int ntiles)
{
    extern __shared__ uint32_t smem[];
    uint32_t* As = smem;                         // [64][132] tf32
    uint32_t* Bb = smem + A_WORDS;               // 4-ring of [16][264]
    const uint32_t As_u = (uint32_t)__cvta_generic_to_shared(As);
    const uint32_t Bu   = (uint32_t)__cvta_generic_to_shared(Bb);

    const int tid = threadIdx.x, lane = tid & 31, wid = tid >> 5;
    const int nCta = gridDim.x;
    const float sh = sp[0], bi = bp[0];
    const size_t vstride = term ? (size_t)32768 : (size_t)256;

    const int nq = wid * 32;                     // warp-private n window
    const int lr = lane >> 2, lc = lane & 3;
    const int lm_mat = lane >> 3, lm_row = lane & 7;
    const int lm_roff = (lm_mat & 1) * 8 + lm_row;
    const int lm_koff = (lm_mat >> 1) * 4;

    auto voff_of = [&](int t) -> size_t {        // V tile base (no m-split)
        int rc = (t >> 1) & 127, b = t >> 8;
        return term ? ((size_t)b * 4194304 + (size_t)rc * 256)
                    : (((size_t)b * 128 + rc) * (size_t)32768);
    };
    auto issue_A = [&](int t) {                  // 64 x 128 raw attn rows
        int mhh = (t & 1) * 64, rc = (t >> 1) & 127, b = t >> 8;
        const float* src = attn + ((size_t)b * 128 + rc) * (size_t)16384
                         + (size_t)mhh * 128;
        #pragma unroll
        for (int q = 0; q < 8; ++q) {
            int c = q * 256 + tid;               // 2048 16B chunks
            int row = c >> 5, w = c & 31;
            cp16(As_u + (uint32_t)row * (A_STRIDE * 4) + (uint32_t)w * 16,
                 src + row * 128 + w * 4);
        }
        CP_COMMIT();
    };
    auto issue_B = [&](int t, int chunk) {       // warp-private 16k x 32n slab
        const float* src = V + voff_of(t) + (size_t)(chunk * KCHUNK) * vstride + nq;
        const uint32_t dst = Bu + (uint32_t)(chunk & 3) * (B_WORDS * 4)
                           + (uint32_t)nq * 4;
        #pragma unroll
        for (int q = 0; q < 4; ++q) {
            int c = q * 32 + lane;               // 128 chunks: 16 rows x 8 x 16B
            int row = c >> 3, g = c & 7;
            cp16(dst + (uint32_t)row * (B_STRIDE * 4) + (uint32_t)g * 16,
                 src + (size_t)row * vstride + g * 4);
        }
        CP_COMMIT();
    };

    int t = blockIdx.x;
    if (t >= ntiles) return;

    issue_A(t);
    issue_B(t, 0); issue_B(t, 1); issue_B(t, 2);

    #pragma unroll 1
    for (; t < ntiles; t += nCta) {
        const bool last = (t + nCta >= ntiles);
        const int mhh = (t & 1) * 64;
        const size_t off = voff_of(t) + (size_t)mhh * vstride;

        // ---- head: A(t) done (B0-2 pending) ----
        CP_WAIT(3);
        __syncthreads();

        // term2 RMW: L2 prefetch of the out half-tile
        if (term) {
            const float* ob = out + off;
            #pragma unroll
            for (int i = 0; i < 2; ++i) {
                int idx = i * 256 + tid;         // 512 x 128B lines
                int row = idx >> 3, lq = idx & 7;
                asm volatile("prefetch.global.L2 [%0];"
                             :: "l"(ob + (size_t)row * vstride + lq * 32));
            }
        }

        // ---- softmax in place (rows global mhh+row; no max pass) ----
        float* Af = (float*)As;
        #pragma unroll 2
        for (int rr = 0; rr < 8; ++rr) {
            int row = wid * 8 + rr;
            float4 v = *(const float4*)(Af + row * A_STRIDE + lane * 4);
            float fr = (float)(mhh + row);
            float e[4]; float sum = 0.f;
            #pragma unroll
            for (int j = 0; j < 4; ++j) {
                float d = (float)(lane * 4 + j) - fr;
                float vv = (j == 0 ? v.x : j == 1 ? v.y : j == 2 ? v.z : v.w)
                           - fmaf(sh, d * d, bi);
                e[j] = __expf(vv);
                sum += e[j];
            }
            #pragma unroll
            for (int o = 16; o > 0; o >>= 1) sum += __shfl_xor_sync(~0u, sum, o);
            float inv = 1.0f / sum;
            uint4 w = make_uint4(tf32u(e[0] * inv), tf32u(e[1] * inv),
                                 tf32u(e[2] * inv), tf32u(e[3] * inv));
            *(uint4*)(As + row * A_STRIDE + lane * 4) = w;
        }
        __syncthreads();

        float acc[4][4][4];
        #pragma unroll
        for (int u = 0; u < 4; ++u)
            #pragma unroll
            for (int j = 0; j < 4; ++j)
                #pragma unroll
                for (int q = 0; q < 4; ++q) acc[u][j][q] = 0.f;

        // ---- 8 k-chunks, fully warp-paced (zero block syncs) ----
        #pragma unroll 1
        for (int c = 0; c < NCHUNK; ++c) {
            if (c <= 5) CP_WAIT(2);
            else if (c == 6) CP_WAIT(1);
            else CP_WAIT(0);

            if (c <= 4) issue_B(t, c + 3);       // buf (c-1)&3: own reads done

            const uint32_t* Bsc = Bb + (c & 3) * B_WORDS;
            #pragma unroll
            for (int ks = 0; ks < 2; ++ks) {
                uint32_t a[4][4];
                #pragma unroll
                for (int u = 0; u < 4; ++u) {
                    uint32_t addr = As_u + (uint32_t)((u * 16 + lm_roff) * A_STRIDE
                                                      + c * KCHUNK + ks * 8 + lm_koff) * 4;
                    ldsm_x4(a[u], addr);
                }
                #pragma unroll
                for (int j = 0; j < 4; ++j) {
                    const float* bp8 = (const float*)Bsc + (ks * 8 + lc) * B_STRIDE
                                       + nq + j * 8 + lr;
                    uint32_t b0 = tf32u(bp8[0]);
                    uint32_t b1 = tf32u(bp8[4 * B_STRIDE]);
                    #pragma unroll
                    for (int u = 0; u < 4; ++u)
                        mma_tf32(acc[u][j], a[u], b0, b1);
                }
            }
        }

        // ---- epilogue ----
        float* obase = out + off;
        #pragma unroll
        for (int u = 0; u < 4; ++u) {
            #pragma unroll
            for (int j = 0; j < 4; ++j) {
                int r0 = u * 16 + lr;
                int col = nq + j * 8 + lc * 2;
                float* p0 = obase + (size_t)r0 * vstride + col;
                float* p1 = p0 + 8 * vstride;
                float2 v0 = make_float2(acc[u][j][0], acc[u][j][1]);
                float2 v1 = make_float2(acc[u][j][2], acc[u][j][3]);
                if (term) {
                    float2 c0 = *(const float2*)p0;
                    float2 c1 = *(const float2*)p1;
                    v0.x += c0.x; v0.y += c0.y;
                    v1.x += c1.x; v1.y += c1.y;
                }
                *(float2*)p0 = v0;
                *(float2*)p1 = v1;
            }
        }

        // ---- tile end: re-converge, then issue everything for t+nCta ----
        __syncthreads();
        if (!last) {
            issue_A(t + nCta);
            issue_B(t + nCta, 0);
            issue_B(t + nCta, 1);
            issue_B(t + nCta, 2);
        }
    }
}

extern "C" void kernel_launch(void* const* d_in, const int* in_sizes, int n_in,
                              void* d_out, int out_size)
{
    const float* attn_x = (const float*)d_in[1];
    const float* attn_y = (const float*)d_in[2];
    const float* V      = (const float*)d_in[3];
    const float* sh     = (const float*)d_in[4];
    const float* bi     = (const float*)d_in[5];
    float* out          = (float*)d_out;

    const int B = in_sizes[3] / (128 * 128 * 256);
    const int ntiles = B * 128 * 2;              // half-tiles

    int nsm = 148;
    cudaDeviceGetAttribute(&nsm, cudaDevAttrMultiProcessorCount, 0);
    int grid = 2 * nsm < ntiles ? 2 * nsm : ntiles;

    cudaFuncSetAttribute(gt_mma, cudaFuncAttributeMaxDynamicSharedMemorySize, SMEM_BYTES);

    gt_mma<<<grid, 256, SMEM_BYTES>>>(attn_x, V, sh, bi, out, 0, ntiles);
    gt_mma<<<grid, 256, SMEM_BYTES>>>(attn_y, V, sh, bi, out, 1, ntiles);
}

// round 14
// speedup vs baseline: 1.3967x; 1.0574x over previous
#include <cuda_runtime.h>
#include <cstdint>

#define A_STRIDE 132                     // words
#define B_STRIDE 264                     // words
#define KCHUNK 16
#define NCHUNK 8
#define A_WORDS (64 * A_STRIDE)          // 8448 (64-row half tile)
#define B_WORDS (KCHUNK * B_STRIDE)      // 4224
#define SMEM_BYTES ((A_WORDS + 4 * B_WORDS) * 4)   // 101376 -> 2 CTAs/SM

static __device__ __forceinline__ uint32_t tf32u(float x) {
    uint32_t r;
    asm("cvt.rna.tf32.f32 %0, %1;" : "=r"(r) : "f"(x));
    return r;
}
static __device__ __forceinline__ void cp16(uint32_t dst, const void* src) {
    asm volatile("cp.async.cg.shared.global [%0], [%1], 16;" :: "r"(dst), "l"(src));
}
#define CP_COMMIT() asm volatile("cp.async.commit_group;" ::: "memory")
#define CP_WAIT(n)  asm volatile("cp.async.wait_group %0;" :: "n"(n) : "memory")

static __device__ __forceinline__ void stcs_f2(float* p, float2 v) {
    asm volatile("st.global.cs.v2.f32 [%0], {%1, %2};"
                 :: "l"(p), "f"(v.x), "f"(v.y) : "memory");
}
static __device__ __forceinline__ void ldsm_x4(uint32_t r[4], uint32_t addr) {
    asm volatile("ldmatrix.sync.aligned.m8n8.x4.shared.b16 {%0,%1,%2,%3}, [%4];"
                 : "=r"(r[0]), "=r"(r[1]), "=r"(r[2]), "=r"(r[3]) : "r"(addr));
}
static __device__ __forceinline__ void mma_tf32(float c[4], const uint32_t a[4],
                                                uint32_t b0, uint32_t b1) {
    asm volatile(
        "mma.sync.aligned.m16n8k8.row.col.f32.tf32.tf32.f32 "
        "{%0,%1,%2,%3}, {%4,%5,%6,%7}, {%8,%9}, {%0,%1,%2,%3};"
        : "+f"(c[0]), "+f"(c[1]), "+f"(c[2]), "+f"(c[3])
        : "r"(a[0]), "r"(a[1]), "r"(a[2]), "r"(a[3]), "r"(b0), "r"(b1));
}

// ---------------------------------------------------------------------------
// Persistent, 256 thr/CTA, 2 CTAs/SM. Half-tile t -> (mhh=(t&1)*64,
// rc=(t>>1)&127, b=t>>8): D[64,256] = softmax(attn[b,rc,mhh..]+g) @ V_t.
// Warp w owns n-cols [w*32, w*32+32): B slab warp-private; zero block syncs
// in chunk loop.  Cross-tile schedule (per-thread cp.async FIFO):
//   c5/c6/c7 issue B(t+1, 0/1/2); post-chunk sync -> issue A(t+1) -> epilogue
//   head: wait(0)  (covered by the preceding epilogue)
//   chunks: c<=2 none; c3..c7 wait(2); last tile: c5 w(2), c6 w(1), c7 w(0).
// ---------------------------------------------------------------------------
__global__ void __launch_bounds__(256, 2) gt_mma(
    const float* __restrict__ attn, const float* __restrict__ V,
    const float* __restrict__ sp, const float* __restrict__ bp,
    float* __restrict__ out, int term, int ntiles)
{
    extern __shared__ uint32_t smem[];
    uint32_t* As = smem;                         // [64][132] tf32
    uint32_t* Bb = smem + A_WORDS;               // 4-ring of [16][264] raw fp32
    const uint32_t As_u = (uint32_t)__cvta_generic_to_shared(As);
    const uint32_t Bu   = (uint32_t)__cvta_generic_to_shared(Bb);

    const int tid = threadIdx.x, lane = tid & 31, wid = tid >> 5;
    const int nCta = gridDim.x;
    const float sh = sp[0], bi = bp[0];
    const size_t vstride = term ? (size_t)32768 : (size_t)256;

    const int nq = wid * 32;
    const int lr = lane >> 2, lc = lane & 3;
    const int lm_mat = lane >> 3, lm_row = lane & 7;
    const int lm_roff = (lm_mat & 1) * 8 + lm_row;
    const int lm_koff = (lm_mat >> 1) * 4;

    auto voff_of = [&](int t) -> size_t {
        int rc = (t >> 1) & 127, b = t >> 8;
        return term ? ((size_t)b * 4194304 + (size_t)rc * 256)
                    : (((size_t)b * 128 + rc) * (size_t)32768);
    };
    auto issue_A = [&](int t) {
        int mhh = (t & 1) * 64, rc = (t >> 1) & 127, b = t >> 8;
        const float* src = attn + ((size_t)b * 128 + rc) * (size_t)16384
                         + (size_t)mhh * 128;
        #pragma unroll
        for (int q = 0; q < 8; ++q) {
            int c = q * 256 + tid;
            int row = c >> 5, w = c & 31;
            cp16(As_u + (uint32_t)row * (A_STRIDE * 4) + (uint32_t)w * 16,
                 src + row * 128 + w * 4);
        }
        CP_COMMIT();
    };
    auto issue_B = [&](int t, int chunk) {       // warp-private 16k x 32n slab
        const float* src = V + voff_of(t) + (size_t)(chunk * KCHUNK) * vstride + nq;
        const uint32_t dst = Bu + (uint32_t)(chunk & 3) * (B_WORDS * 4)
                           + (uint32_t)nq * 4;
        #pragma unroll
        for (int q = 0; q < 4; ++q) {
            int c = q * 32 + lane;
            int row = c >> 3, g = c & 7;
            cp16(dst + (uint32_t)row * (B_STRIDE * 4) + (uint32_t)g * 16,
                 src + (size_t)row * vstride + g * 4);
        }
        CP_COMMIT();
    };

    int t = blockIdx.x;
    if (t >= ntiles) return;

    issue_A(t);
    issue_B(t, 0); issue_B(t, 1); issue_B(t, 2);

    #pragma unroll 1
    for (; t < ntiles; t += nCta) {
        const bool last = (t + nCta >= ntiles);
        const int mhh = (t & 1) * 64;
        const size_t off = voff_of(t) + (size_t)mhh * vstride;

        // term2 RMW: L2 prefetch (independent of smem; before the wait)
        if (term) {
            const float* ob = out + off;
            #pragma unroll
            for (int i = 0; i < 2; ++i) {
                int idx = i * 256 + tid;         // 512 x 128B lines
                int row = idx >> 3, lq = idx & 7;
                asm volatile("prefetch.global.L2 [%0];"
                             :: "l"(ob + (size_t)row * vstride + lq * 32));
            }
        }

        // ---- head: everything for tile t drained (covered by prev epilogue) ----
        CP_WAIT(0);
        __syncthreads();

        // ---- softmax in place (no max pass; exponents bounded) ----
        float* Af = (float*)As;
        #pragma unroll 2
        for (int rr = 0; rr < 8; ++rr) {
            int row = wid * 8 + rr;
            float4 v = *(const float4*)(Af + row * A_STRIDE + lane * 4);
            float fr = (float)(mhh + row);
            float e[4]; float sum = 0.f;
            #pragma unroll
            for (int j = 0; j < 4; ++j) {
                float d = (float)(lane * 4 + j) - fr;
                float vv = (j == 0 ? v.x : j == 1 ? v.y : j == 2 ? v.z : v.w)
                           - fmaf(sh, d * d, bi);
                e[j] = __expf(vv);
                sum += e[j];
            }
            #pragma unroll
            for (int o = 16; o > 0; o >>= 1) sum += __shfl_xor_sync(~0u, sum, o);
            float inv = 1.0f / sum;
            uint4 w = make_uint4(tf32u(e[0] * inv), tf32u(e[1] * inv),
                                 tf32u(e[2] * inv), tf32u(e[3] * inv));
            *(uint4*)(As + row * A_STRIDE + lane * 4) = w;
        }
        __syncthreads();

        float acc[4][4][4];
        #pragma unroll
        for (int u = 0; u < 4; ++u)
            #pragma unroll
            for (int j = 0; j < 4; ++j)
                #pragma unroll
                for (int q = 0; q < 4; ++q) acc[u][j][q] = 0.f;

        // ---- 8 k-chunks, warp-paced (zero block syncs) ----
        #pragma unroll 1
        for (int c = 0; c < NCHUNK; ++c) {
            if (c >= 3) {
                if (!last || c <= 5) CP_WAIT(2);
                else if (c == 6) CP_WAIT(1);
                else CP_WAIT(0);
            }

            if (c <= 4) issue_B(t, c + 3);
            else if (!last) issue_B(t + nCta, c - 5);   // buf (c-5): own reads done at c-1

            const uint32_t* Bsc = Bb + (c & 3) * B_WORDS;
            #pragma unroll
            for (int ks = 0; ks < 2; ++ks) {
                uint32_t a[4][4];
                #pragma unroll
                for (int u = 0; u < 4; ++u) {
                    uint32_t addr = As_u + (uint32_t)((u * 16 + lm_roff) * A_STRIDE
                                                      + c * KCHUNK + ks * 8 + lm_koff) * 4;
                    ldsm_x4(a[u], addr);
                }
                #pragma unroll
                for (int j = 0; j < 4; ++j) {
                    // raw fp32 bits: HW truncates to tf32 (saves 16 cvt/chunk)
                    const uint32_t* bp8 = Bsc + (ks * 8 + lc) * B_STRIDE + nq + j * 8 + lr;
                    uint32_t b0 = bp8[0];
                    uint32_t b1 = bp8[4 * B_STRIDE];
                    #pragma unroll
                    for (int u = 0; u < 4; ++u)
                        mma_tf32(acc[u][j], a[u], b0, b1);
                }
            }
        }

        // ---- A reads done everywhere -> start A(t+1) DMA under the epilogue ----
        __syncthreads();
        if (!last) issue_A(t + nCta);

        // ---- epilogue ----
        float* obase = out + off;
        #pragma unroll
        for (int u = 0; u < 4; ++u) {
            #pragma unroll
            for (int j = 0; j < 4; ++j) {
                int r0 = u * 16 + lr;
                int col = nq + j * 8 + lc * 2;
                float* p0 = obase + (size_t)r0 * vstride + col;
                float* p1 = p0 + 8 * vstride;
                float2 v0 = make_float2(acc[u][j][0], acc[u][j][1]);
                float2 v1 = make_float2(acc[u][j][2], acc[u][j][3]);
                if (term) {
                    float2 c0 = *(const float2*)p0;
                    float2 c1 = *(const float2*)p1;
                    v0.x += c0.x; v0.y += c0.y;
                    v1.x += c1.x; v1.y += c1.y;
                    stcs_f2(p0, v0);             // dead after this kernel: evict-stream
                    stcs_f2(p1, v1);
                } else {
                    *(float2*)p0 = v0;           // re-read by term2: keep in L2
                    *(float2*)p1 = v1;
                }
            }
        }
    }
}

extern "C" void kernel_launch(void* const* d_in, const int* in_sizes, int n_in,
                              void* d_out, int out_size)
{
    const float* attn_x = (const float*)d_in[1];
    const float* attn_y = (const float*)d_in[2];
    const float* V      = (const float*)d_in[3];
    const float* sh     = (const float*)d_in[4];
    const float* bi     = (const float*)d_in[5];
    float* out          = (float*)d_out;

    const int B = in_sizes[3] / (128 * 128 * 256);
    const int ntiles = B * 128 * 2;              // half-tiles

    int nsm = 148;
    cudaDeviceGetAttribute(&nsm, cudaDevAttrMultiProcessorCount, 0);
    int grid = 2 * nsm < ntiles ? 2 * nsm : ntiles;

    cudaFuncSetAttribute(gt_mma, cudaFuncAttributeMaxDynamicSharedMemorySize, SMEM_BYTES);

    gt_mma<<<grid, 256, SMEM_BYTES>>>(attn_x, V, sh, bi, out, 0, ntiles);
    gt_mma<<<grid, 256, SMEM_BYTES>>>(attn_y, V, sh, bi, out, 1, ntiles);
}

// round 15
// speedup vs baseline: 1.4962x; 1.0712x over previous
#include <cuda_runtime.h>
#include <cstdint>

#define A_STRIDE 132                     // words
#define B_STRIDE 264                     // words
#define KCHUNK 16
#define NCHUNK 8
#define A_WORDS (64 * A_STRIDE)          // 8448 (64-row half tile)
#define B_WORDS (KCHUNK * B_STRIDE)      // 4224
#define SMEM_BYTES ((A_WORDS + 4 * B_WORDS) * 4)   // 101376 -> 2 CTAs/SM

static __device__ __forceinline__ uint32_t tf32u(float x) {
    uint32_t r;
    asm("cvt.rna.tf32.f32 %0, %1;" : "=r"(r) : "f"(x));
    return r;
}
static __device__ __forceinline__ void cp16(uint32_t dst, const void* src) {
    asm volatile("cp.async.cg.shared.global [%0], [%1], 16;" :: "r"(dst), "l"(src));
}
#define CP_COMMIT() asm volatile("cp.async.commit_group;" ::: "memory")
#define CP_WAIT(n)  asm volatile("cp.async.wait_group %0;" :: "n"(n) : "memory")

// fire-and-forget L2-side float add (no return latency)
static __device__ __forceinline__ void red2_f32(float* p, float2 v) {
    asm volatile("red.global.add.f32 [%0], %1;"   :: "l"(p), "f"(v.x) : "memory");
    asm volatile("red.global.add.f32 [%0+4], %1;" :: "l"(p), "f"(v.y) : "memory");
}
static __device__ __forceinline__ void ldsm_x4(uint32_t r[4], uint32_t addr) {
    asm volatile("ldmatrix.sync.aligned.m8n8.x4.shared.b16 {%0,%1,%2,%3}, [%4];"
                 : "=r"(r[0]), "=r"(r[1]), "=r"(r[2]), "=r"(r[3]) : "r"(addr));
}
static __device__ __forceinline__ void mma_tf32(float c[4], const uint32_t a[4],
                                                uint32_t b0, uint32_t b1) {
    asm volatile(
        "mma.sync.aligned.m16n8k8.row.col.f32.tf32.tf32.f32 "
        "{%0,%1,%2,%3}, {%4,%5,%6,%7}, {%8,%9}, {%0,%1,%2,%3};"
        : "+f"(c[0]), "+f"(c[1]), "+f"(c[2]), "+f"(c[3])
        : "r"(a[0]), "r"(a[1]), "r"(a[2]), "r"(a[3]), "r"(b0), "r"(b1));
}

// ---------------------------------------------------------------------------
// Persistent, 256 thr/CTA, 2 CTAs/SM. Half-tile t -> (mhh=(t&1)*64,
// rc=(t>>1)&127, b=t>>8): D[64,256] = softmax(attn[b,rc,mhh..]+g) @ V_t.
// Warp w owns n-cols [w*32, w*32+32): B slab warp-private; zero block syncs
// in chunk loop.  Cross-tile schedule (per-thread cp.async FIFO):
//   c5/c6/c7 issue B(t+1, 0/1/2); post-chunk sync -> issue A(t+1) -> epilogue
//   head: wait(0); chunks: c<=2 none, c3..c7 wait(2); last tile 2/1/0 tail.
// term1 epilogue: plain stores (kept in L2 for term2).
// term2 epilogue: red.global.add (no load latency, half the LTS ops).
// ---------------------------------------------------------------------------
__global__ void __launch_bounds__(256, 2) gt_mma(
    const float* __restrict__ attn, const float* __restrict__ V,
    const float* __restrict__ sp, const float* __restrict__ bp,
    float* __restrict__ out, int term, int ntiles)
{
    extern __shared__ uint32_t smem[];
    uint32_t* As = smem;                         // [64][132] tf32
    uint32_t* Bb = smem + A_WORDS;               // 4-ring of [16][264] raw fp32
    const uint32_t As_u = (uint32_t)__cvta_generic_to_shared(As);
    const uint32_t Bu   = (uint32_t)__cvta_generic_to_shared(Bb);

    const int tid = threadIdx.x, lane = tid & 31, wid = tid >> 5;
    const int nCta = gridDim.x;
    const float sh = sp[0], bi = bp[0];
    const size_t vstride = term ? (size_t)32768 : (size_t)256;

    const int nq = wid * 32;
    const int lr = lane >> 2, lc = lane & 3;
    const int lm_mat = lane >> 3, lm_row = lane & 7;
    const int lm_roff = (lm_mat & 1) * 8 + lm_row;
    const int lm_koff = (lm_mat >> 1) * 4;

    auto voff_of = [&](int t) -> size_t {
        int rc = (t >> 1) & 127, b = t >> 8;
        return term ? ((size_t)b * 4194304 + (size_t)rc * 256)
                    : (((size_t)b * 128 + rc) * (size_t)32768);
    };
    auto issue_A = [&](int t) {
        int mhh = (t & 1) * 64, rc = (t >> 1) & 127, b = t >> 8;
        const float* src = attn + ((size_t)b * 128 + rc) * (size_t)16384
                         + (size_t)mhh * 128;
        #pragma unroll
        for (int q = 0; q < 8; ++q) {
            int c = q * 256 + tid;
            int row = c >> 5, w = c & 31;
            cp16(As_u + (uint32_t)row * (A_STRIDE * 4) + (uint32_t)w * 16,
                 src + row * 128 + w * 4);
        }
        CP_COMMIT();
    };
    auto issue_B = [&](int t, int chunk) {       // warp-private 16k x 32n slab
        const float* src = V + voff_of(t) + (size_t)(chunk * KCHUNK) * vstride + nq;
        const uint32_t dst = Bu + (uint32_t)(chunk & 3) * (B_WORDS * 4)
                           + (uint32_t)nq * 4;
        #pragma unroll
        for (int q = 0; q < 4; ++q) {
            int c = q * 32 + lane;
            int row = c >> 3, g = c & 7;
            cp16(dst + (uint32_t)row * (B_STRIDE * 4) + (uint32_t)g * 16,
                 src + (size_t)row * vstride + g * 4);
        }
        CP_COMMIT();
    };

    int t = blockIdx.x;
    if (t >= ntiles) return;

    issue_A(t);
    issue_B(t, 0); issue_B(t, 1); issue_B(t, 2);

    #pragma unroll 1
    for (; t < ntiles; t += nCta) {
        const bool last = (t + nCta >= ntiles);
        const int mhh = (t & 1) * 64;
        const size_t off = voff_of(t) + (size_t)mhh * vstride;

        // ---- head: everything for tile t drained (covered by prev epilogue) ----
        CP_WAIT(0);
        __syncthreads();

        // ---- softmax in place (no max pass; exponents bounded) ----
        float* Af = (float*)As;
        #pragma unroll 2
        for (int rr = 0; rr < 8; ++rr) {
            int row = wid * 8 + rr;
            float4 v = *(const float4*)(Af + row * A_STRIDE + lane * 4);
            float fr = (float)(mhh + row);
            float e[4]; float sum = 0.f;
            #pragma unroll
            for (int j = 0; j < 4; ++j) {
                float d = (float)(lane * 4 + j) - fr;
                float vv = (j == 0 ? v.x : j == 1 ? v.y : j == 2 ? v.z : v.w)
                           - fmaf(sh, d * d, bi);
                e[j] = __expf(vv);
                sum += e[j];
            }
            #pragma unroll
            for (int o = 16; o > 0; o >>= 1) sum += __shfl_xor_sync(~0u, sum, o);
            float inv = 1.0f / sum;
            uint4 w = make_uint4(tf32u(e[0] * inv), tf32u(e[1] * inv),
                                 tf32u(e[2] * inv), tf32u(e[3] * inv));
            *(uint4*)(As + row * A_STRIDE + lane * 4) = w;
        }
        __syncthreads();

        float acc[4][4][4];
        #pragma unroll
        for (int u = 0; u < 4; ++u)
            #pragma unroll
            for (int j = 0; j < 4; ++j)
                #pragma unroll
                for (int q = 0; q < 4; ++q) acc[u][j][q] = 0.f;

        // ---- 8 k-chunks, warp-paced (zero block syncs) ----
        #pragma unroll 1
        for (int c = 0; c < NCHUNK; ++c) {
            if (c >= 3) {
                if (!last || c <= 5) CP_WAIT(2);
                else if (c == 6) CP_WAIT(1);
                else CP_WAIT(0);
            }

            if (c <= 4) issue_B(t, c + 3);
            else if (!last) issue_B(t + nCta, c - 5);   // buf (c-5): own reads done at c-1

            const uint32_t* Bsc = Bb + (c & 3) * B_WORDS;
            #pragma unroll
            for (int ks = 0; ks < 2; ++ks) {
                uint32_t a[4][4];
                #pragma unroll
                for (int u = 0; u < 4; ++u) {
                    uint32_t addr = As_u + (uint32_t)((u * 16 + lm_roff) * A_STRIDE
                                                      + c * KCHUNK + ks * 8 + lm_koff) * 4;
                    ldsm_x4(a[u], addr);
                }
                #pragma unroll
                for (int j = 0; j < 4; ++j) {
                    // raw fp32 bits: HW truncates to tf32
                    const uint32_t* bp8 = Bsc + (ks * 8 + lc) * B_STRIDE + nq + j * 8 + lr;
                    uint32_t b0 = bp8[0];
                    uint32_t b1 = bp8[4 * B_STRIDE];
                    #pragma unroll
                    for (int u = 0; u < 4; ++u)
                        mma_tf32(acc[u][j], a[u], b0, b1);
                }
            }
        }

        // ---- A reads done everywhere -> start A(t+1) DMA under the epilogue ----
        __syncthreads();
        if (!last) issue_A(t + nCta);

        // ---- epilogue ----
        float* obase = out + off;
        #pragma unroll
        for (int u = 0; u < 4; ++u) {
            #pragma unroll
            for (int j = 0; j < 4; ++j) {
                int r0 = u * 16 + lr;
                int col = nq + j * 8 + lc * 2;
                float* p0 = obase + (size_t)r0 * vstride + col;
                float* p1 = p0 + 8 * vstride;
                float2 v0 = make_float2(acc[u][j][0], acc[u][j][1]);
                float2 v1 = make_float2(acc[u][j][2], acc[u][j][3]);
                if (term) {
                    red2_f32(p0, v0);            // L2-side add: no return latency
                    red2_f32(p1, v1);
                } else {
                    *(float2*)p0 = v0;           // re-read by term2: keep in L2
                    *(float2*)p1 = v1;
                }
            }
        }
    }
}

extern "C" void kernel_launch(void* const* d_in, const int* in_sizes, int n_in,
                              void* d_out, int out_size)
{
    const float* attn_x = (const float*)d_in[1];
    const float* attn_y = (const float*)d_in[2];
    const float* V      = (const float*)d_in[3];
    const float* sh     = (const float*)d_in[4];
    const float* bi     = (const float*)d_in[5];
    float* out          = (float*)d_out;

    const int B = in_sizes[3] / (128 * 128 * 256);
    const int ntiles = B * 128 * 2;              // half-tiles

    int nsm = 148;
    cudaDeviceGetAttribute(&nsm, cudaDevAttrMultiProcessorCount, 0);
    int grid = 2 * nsm < ntiles ? 2 * nsm : ntiles;

    cudaFuncSetAttribute(gt_mma, cudaFuncAttributeMaxDynamicSharedMemorySize, SMEM_BYTES);

    gt_mma<<<grid, 256, SMEM_BYTES>>>(attn_x, V, sh, bi, out, 0, ntiles);
    gt_mma<<<grid, 256, SMEM_BYTES>>>(attn_y, V, sh, bi, out, 1, ntiles);
}